// round 5
// baseline (speedup 1.0000x reference)
#include <cuda_runtime.h>
#include <cstdint>

#define NN   100000
#define NNP  100096   // 782 * 128 (padded M)
#define NE   1600000
#define DD   128
#define KK   512      // 3*D (relations) + D (self)
#define LL   3
#define NTILE 782     // gemm tiles of 128 nodes
#define NAGG  12500   // agg CTAs (8 nodes each)
#define LAG   512     // agg head-start in bids

// ---------------- device scratch (static: no allocation allowed) ----------------
__device__ float    g_agg[(size_t)NNP * KK];     // [node][512]: rel0|rel1|rel2|rna(h)
__device__ float    g_h[2][(size_t)NN * DD];     // ping-pong hidden states
__device__ float    g_bt[LL][DD][KK];            // transposed+rna weights: Bt[l][j][k]
__device__ int      g_deg[NN];
__device__ int      g_off[NN + 1];
__device__ int      g_cur[NN];
__device__ unsigned g_csr[NE];                   // src | (etype<<20)
__device__ int      g_bsum[128];
__device__ int      g_done[LL][NTILE];           // per-layer tile completion counters

// ---------------- small helpers ----------------
__device__ __forceinline__ uint32_t smem_u32(const void* p) {
    uint32_t a;
    asm("{ .reg .u64 t; cvta.to.shared.u64 t, %1; cvt.u32.u64 %0, t; }" : "=r"(a) : "l"(p));
    return a;
}
__device__ __forceinline__ float rna_tf32(float x) {
    uint32_t u;
    asm("cvt.rna.tf32.f32 %0, %1;" : "=r"(u) : "f"(x));
    return __uint_as_float(u);
}

// ---------------- CSR construction (key = dst, etype packed in csr entry) -------
__global__ void k_zero_deg() {   // also zeroes the per-layer done flags
    int i = blockIdx.x * 256 + threadIdx.x;
    if (i < NN) g_deg[i] = 0;
    if (i < LL * NTILE) (&g_done[0][0])[i] = 0;
}
__global__ void k_hist(const int* __restrict__ dst) {
    int e = blockIdx.x * 256 + threadIdx.x;
    if (e < NE) atomicAdd(&g_deg[__ldg(&dst[e])], 1);
}
__global__ void k_scan1() {
    __shared__ int s[1024];
    int t = threadIdx.x;
    int i = blockIdx.x * 1024 + t;
    int v = (i < NN) ? g_deg[i] : 0;
    s[t] = v;
    __syncthreads();
    #pragma unroll
    for (int d = 1; d < 1024; d <<= 1) {
        int x = (t >= d) ? s[t - d] : 0;
        __syncthreads();
        s[t] += x;
        __syncthreads();
    }
    if (i < NN) g_off[i + 1] = s[t];
    if (t == 1023) g_bsum[blockIdx.x] = s[1023];
}
__global__ void k_scan2() {
    if (threadIdx.x == 0) {
        int run = 0;
        for (int b = 0; b < 98; b++) { int x = g_bsum[b]; g_bsum[b] = run; run += x; }
    }
}
__global__ void k_scan3() {   // finalize offsets AND write cursors
    int t = threadIdx.x;
    int i = blockIdx.x * 1024 + t;
    if (i < NN) {
        int v = g_off[i + 1] + g_bsum[blockIdx.x];
        g_off[i + 1] = v;
        g_cur[i + 1] = v;
    }
    if (i == 0) { g_off[0] = 0; g_cur[0] = 0; }
}
__global__ void k_scatter(const int* __restrict__ src, const int* __restrict__ dst,
                          const int* __restrict__ ety) {
    int e = blockIdx.x * 256 + threadIdx.x;
    if (e < NE) {
        int d = __ldg(&dst[e]);
        int pos = atomicAdd(&g_cur[d], 1);
        g_csr[pos] = (unsigned)__ldg(&src[e]) | ((unsigned)__ldg(&ety[e]) << 20);
    }
}

// ---------------- weight transpose + tf32 rounding ----------------
__global__ void k_wt(const float* __restrict__ W, const float* __restrict__ Ws) {
    int idx = blockIdx.x * 256 + threadIdx.x;
    if (idx < LL * DD * KK) {
        int l = idx / (DD * KK);
        int rem = idx % (DD * KK);
        int j = rem / KK;
        int k = rem % KK;
        float v = (k < 384)
            ? W[(((size_t)l * 3 + (k >> 7)) * DD + (k & 127)) * DD + j]
            : Ws[((size_t)l * DD + (k - 384)) * DD + j];
        (&g_bt[0][0][0])[idx] = rna_tf32(v);
    }
}

// ---------------- unified layer kernel: interleaved agg + gemm CTAs ----------------
static constexpr int GM_STAGES  = 3;
static constexpr int ROW_PAD    = 36;
static constexpr int TILE_FLTS  = 128 * ROW_PAD;
static constexpr int STAGE_FLTS = 2 * TILE_FLTS;
static constexpr int GEMM_SMEM  = GM_STAGES * STAGE_FLTS * 4;   // 110592 bytes
static constexpr int GRID_LAYER = LAG + NTILE * 17;             // 13806

__device__ __forceinline__ void mma_tf32_16x8x8(float c[4],
                                                uint32_t a0, uint32_t a1, uint32_t a2, uint32_t a3,
                                                uint32_t b0, uint32_t b1) {
    asm volatile(
        "mma.sync.aligned.m16n8k8.row.col.f32.tf32.tf32.f32 "
        "{%0,%1,%2,%3}, {%4,%5,%6,%7}, {%8,%9}, {%0,%1,%2,%3};"
        : "+f"(c[0]), "+f"(c[1]), "+f"(c[2]), "+f"(c[3])
        : "r"(a0), "r"(a1), "r"(a2), "r"(a3), "r"(b0), "r"(b1));
}

__device__ void do_agg(int a, const float4* __restrict__ h4, int* __restrict__ done) {
    int wid = threadIdx.x >> 5, lane = threadIdx.x & 31;
    int node = a * 8 + wid;
    if (node < NN) {
        int e0 = g_off[node], e1 = g_off[node + 1];
        float4 a0 = {0, 0, 0, 0}, a1 = {0, 0, 0, 0}, a2 = {0, 0, 0, 0};

        auto acc = [&](unsigned t, const float4& v) {
            if (t == 0)      { a0.x += v.x; a0.y += v.y; a0.z += v.z; a0.w += v.w; }
            else if (t == 1) { a1.x += v.x; a1.y += v.y; a1.z += v.z; a1.w += v.w; }
            else             { a2.x += v.x; a2.y += v.y; a2.z += v.z; a2.w += v.w; }
        };

        int e = e0;
        for (; e + 3 < e1; e += 4) {
            unsigned p0 = __ldcs(&g_csr[e]);
            unsigned p1 = __ldcs(&g_csr[e + 1]);
            unsigned p2 = __ldcs(&g_csr[e + 2]);
            unsigned p3 = __ldcs(&g_csr[e + 3]);
            float4 v0 = __ldg(&h4[(size_t)(p0 & 0xFFFFFu) * 32 + lane]);
            float4 v1 = __ldg(&h4[(size_t)(p1 & 0xFFFFFu) * 32 + lane]);
            float4 v2 = __ldg(&h4[(size_t)(p2 & 0xFFFFFu) * 32 + lane]);
            float4 v3 = __ldg(&h4[(size_t)(p3 & 0xFFFFFu) * 32 + lane]);
            acc(p0 >> 20, v0);
            acc(p1 >> 20, v1);
            acc(p2 >> 20, v2);
            acc(p3 >> 20, v3);
        }
        for (; e < e1; e++) {
            unsigned p0 = __ldcs(&g_csr[e]);
            float4 v0 = __ldg(&h4[(size_t)(p0 & 0xFFFFFu) * 32 + lane]);
            acc(p0 >> 20, v0);
        }

        float4 s3 = __ldg(&h4[(size_t)node * 32 + lane]);
        auto rna4 = [](float4 v) {
            float4 r;
            r.x = rna_tf32(v.x); r.y = rna_tf32(v.y); r.z = rna_tf32(v.z); r.w = rna_tf32(v.w);
            return r;
        };
        float4* o = reinterpret_cast<float4*>(g_agg) + (size_t)node * 128;
        __stcs(&o[lane],      rna4(a0));
        __stcs(&o[32 + lane], rna4(a1));
        __stcs(&o[64 + lane], rna4(a2));
        __stcs(&o[96 + lane], rna4(s3));
    }
    __threadfence();
    __syncthreads();
    if (threadIdx.x == 0) atomicAdd(&done[a >> 4], 1);   // CTA's 8 nodes share one tile
}

__device__ void do_gemm(int t, const float* __restrict__ B, const float* __restrict__ bias,
                        float* __restrict__ hout, int* __restrict__ done, float* sm) {
    // wait for the 16 (or 4 for last tile) producer CTAs of this tile
    if (threadIdx.x == 0) {
        int need = min(16, NAGG - 16 * t);
        volatile int* f = done + t;
        while (*f < need) __nanosleep(64);
    }
    __syncthreads();   // all threads ordered after the flag observation

    uint32_t smaddr = smem_u32(sm);
    int tid = threadIdx.x, wid = tid >> 5, lane = tid & 31;
    int warp_m = wid >> 1, warp_n = wid & 1;
    int g = lane >> 2, q = lane & 3;

    const float* A = g_agg;
    size_t row0 = (size_t)t * 128;

    uint64_t pol;
    asm volatile("createpolicy.fractional.L2::evict_first.b64 %0;" : "=l"(pol));

    int r_ld[4], c_ld[4];
    #pragma unroll
    for (int i = 0; i < 4; i++) {
        int u = tid + i * 256;
        r_ld[i] = u >> 3;
        c_ld[i] = u & 7;
    }

    auto load_chunk = [&](int kc) {
        int st = kc % GM_STAGES;
        uint32_t sA = smaddr + (uint32_t)(st * STAGE_FLTS) * 4u;
        uint32_t sB = sA + (uint32_t)TILE_FLTS * 4u;
        #pragma unroll
        for (int i = 0; i < 4; i++) {
            const float* gsrc = A + (row0 + (size_t)r_ld[i]) * KK + kc * 32 + c_ld[i] * 4;
            uint32_t d = sA + (uint32_t)(r_ld[i] * ROW_PAD + c_ld[i] * 4) * 4u;
            asm volatile("cp.async.cg.shared.global.L2::cache_hint [%0], [%1], 16, %2;"
                         :: "r"(d), "l"(gsrc), "l"(pol));
        }
        #pragma unroll
        for (int i = 0; i < 4; i++) {
            const float* gsrc = B + (size_t)r_ld[i] * KK + kc * 32 + c_ld[i] * 4;
            uint32_t d = sB + (uint32_t)(r_ld[i] * ROW_PAD + c_ld[i] * 4) * 4u;
            asm volatile("cp.async.cg.shared.global [%0], [%1], 16;" :: "r"(d), "l"(gsrc));
        }
        asm volatile("cp.async.commit_group;" ::: "memory");
    };

    float acc[2][8][4];
    #pragma unroll
    for (int mt = 0; mt < 2; mt++)
        #pragma unroll
        for (int nt = 0; nt < 8; nt++)
            #pragma unroll
            for (int v = 0; v < 4; v++) acc[mt][nt][v] = 0.0f;

    load_chunk(0);
    load_chunk(1);

    const uint32_t* smu = reinterpret_cast<const uint32_t*>(sm);

    #pragma unroll
    for (int kc = 0; kc < 16; kc++) {
        if (kc < 14) asm volatile("cp.async.wait_group 1;" ::: "memory");
        else         asm volatile("cp.async.wait_group 0;" ::: "memory");
        __syncthreads();

        if (kc + 2 < 16) load_chunk(kc + 2);

        int st = kc % GM_STAGES;
        const uint32_t* tA = smu + st * STAGE_FLTS;
        const uint32_t* tB = tA + TILE_FLTS;

        #pragma unroll
        for (int k8 = 0; k8 < 4; k8++) {
            int k0 = k8 * 8;
            uint32_t af[2][4];
            #pragma unroll
            for (int mt = 0; mt < 2; mt++) {
                int rb = warp_m * 32 + mt * 16;
                af[mt][0] = tA[(rb + g)     * ROW_PAD + k0 + q];
                af[mt][1] = tA[(rb + g + 8) * ROW_PAD + k0 + q];
                af[mt][2] = tA[(rb + g)     * ROW_PAD + k0 + q + 4];
                af[mt][3] = tA[(rb + g + 8) * ROW_PAD + k0 + q + 4];
            }
            #pragma unroll
            for (int nt = 0; nt < 8; nt++) {
                int nb = warp_n * 64 + nt * 8;
                uint32_t b0 = tB[(nb + g) * ROW_PAD + k0 + q];
                uint32_t b1 = tB[(nb + g) * ROW_PAD + k0 + q + 4];
                mma_tf32_16x8x8(acc[0][nt], af[0][0], af[0][1], af[0][2], af[0][3], b0, b1);
                mma_tf32_16x8x8(acc[1][nt], af[1][0], af[1][1], af[1][2], af[1][3], b0, b1);
            }
        }
        __syncthreads();
    }

    #pragma unroll
    for (int mt = 0; mt < 2; mt++) {
        size_t r0 = row0 + (size_t)(warp_m * 32 + mt * 16 + g);
        size_t r1 = r0 + 8;
        #pragma unroll
        for (int nt = 0; nt < 8; nt++) {
            int cb = warp_n * 64 + nt * 8 + q * 2;
            float bz0 = __ldg(&bias[cb]), bz1 = __ldg(&bias[cb + 1]);
            if (r0 < NN) {
                hout[r0 * DD + cb]     = acc[mt][nt][0] + bz0;
                hout[r0 * DD + cb + 1] = acc[mt][nt][1] + bz1;
            }
            if (r1 < NN) {
                hout[r1 * DD + cb]     = acc[mt][nt][2] + bz0;
                hout[r1 * DD + cb + 1] = acc[mt][nt][3] + bz1;
            }
        }
    }
}

__global__ void __launch_bounds__(256, 2)
k_layer(const float4* __restrict__ h4, int layer, const float* __restrict__ bias,
        float* __restrict__ hout) {
    extern __shared__ float sm[];
    int* done = &g_done[layer][0];
    const float* B = &g_bt[layer][0][0];

    int b = blockIdx.x;
    if (b < LAG) {                       // agg head-start
        do_agg(b, h4, done);
        return;
    }
    int r = b - LAG;
    int grp = r / 17, pos = r % 17;
    if (pos == 16) {                     // gemm CTA for tile grp
        do_gemm(grp, B, bias, hout, done, sm);
    } else {                             // agg CTA
        int a = LAG + grp * 16 + pos;
        if (a < NAGG) do_agg(a, h4, done);
    }
}

// ---------------- launch ----------------
extern "C" void kernel_launch(void* const* d_in, const int* in_sizes, int n_in,
                              void* d_out, int out_size) {
    const float* feat = (const float*)d_in[0];
    const float* W    = (const float*)d_in[1];
    const float* Ws   = (const float*)d_in[2];
    const float* bias = (const float*)d_in[3];
    const int*   src  = (const int*)d_in[4];
    const int*   dst  = (const int*)d_in[5];
    const int*   ety  = (const int*)d_in[6];
    float*       out  = (float*)d_out;

    static int smem_set = 0;
    if (!smem_set) {
        cudaFuncSetAttribute(k_layer, cudaFuncAttributeMaxDynamicSharedMemorySize, GEMM_SMEM);
        smem_set = 1;
    }

    void* hsym = nullptr;
    cudaGetSymbolAddress(&hsym, g_h);
    float* h0 = (float*)hsym;
    float* h1 = h0 + (size_t)NN * DD;

    // CSR by dst (graph fixed across layers -> build once per launch) + flag reset
    k_zero_deg<<<(NN + 255) / 256, 256>>>();
    k_hist<<<(NE + 255) / 256, 256>>>(dst);
    k_scan1<<<98, 1024>>>();
    k_scan2<<<1, 32>>>();
    k_scan3<<<98, 1024>>>();
    k_scatter<<<(NE + 255) / 256, 256>>>(src, dst, ety);
    k_wt<<<(LL * DD * KK + 255) / 256, 256>>>(W, Ws);

    const float* hin = feat;
    for (int l = 0; l < LL; l++) {
        float* ho = (l == 2) ? out : (l == 0 ? h0 : h1);
        k_layer<<<GRID_LAYER, 256, GEMM_SMEM>>>((const float4*)hin, l, bias + l * DD, ho);
        hin = ho;
    }
}

// round 6
// speedup vs baseline: 1.8771x; 1.8771x over previous
#include <cuda_runtime.h>
#include <cstdint>

#define NN   100000
#define NNP  100096   // 782 * 128 (padded M)
#define NE   1600000
#define DD   128
#define KA   384      // agg intermediate width (3 relations only)
#define KK   512      // GEMM K: 384 (relations) + 128 (self)
#define LL   3
#define NTILE 782
#define CUT  61056    // nodes >= CUT: agg stores evict-normal (L2 tail for reverse gemm)

// ---------------- device scratch (static: no allocation allowed) ----------------
__device__ float    g_agg[(size_t)NNP * KA];     // [node][384]: rel0|rel1|rel2
__device__ float    g_h[2][(size_t)NNP * DD];    // ping-pong hidden states (tf32-valued)
__device__ float    g_hf[(size_t)NNP * DD];      // rna(features) for layer 0
__device__ float    g_bt[LL][DD][KK];            // transposed+rna weights: Bt[l][j][k]
__device__ int      g_deg[NN];
__device__ int      g_off[NN + 1];
__device__ int      g_cur[NN];
__device__ unsigned g_csr[NE];                   // src | (etype<<20)
__device__ int      g_bsum[128];

// ---------------- small helpers ----------------
__device__ __forceinline__ uint32_t smem_u32(const void* p) {
    uint32_t a;
    asm("{ .reg .u64 t; cvta.to.shared.u64 t, %1; cvt.u32.u64 %0, t; }" : "=r"(a) : "l"(p));
    return a;
}
__device__ __forceinline__ float rna_tf32(float x) {
    uint32_t u;
    asm("cvt.rna.tf32.f32 %0, %1;" : "=r"(u) : "f"(x));
    return __uint_as_float(u);
}

// ---------------- CSR construction (key = dst, etype packed in csr entry) -------
__global__ void k_zero_deg() {
    int i = blockIdx.x * 256 + threadIdx.x;
    if (i < NN) g_deg[i] = 0;
}
__global__ void k_hist(const int* __restrict__ dst) {
    int e = blockIdx.x * 256 + threadIdx.x;
    if (e < NE) atomicAdd(&g_deg[__ldg(&dst[e])], 1);
}
__global__ void k_scan1() {
    __shared__ int s[1024];
    int t = threadIdx.x;
    int i = blockIdx.x * 1024 + t;
    int v = (i < NN) ? g_deg[i] : 0;
    s[t] = v;
    __syncthreads();
    #pragma unroll
    for (int d = 1; d < 1024; d <<= 1) {
        int x = (t >= d) ? s[t - d] : 0;
        __syncthreads();
        s[t] += x;
        __syncthreads();
    }
    if (i < NN) g_off[i + 1] = s[t];
    if (t == 1023) g_bsum[blockIdx.x] = s[1023];
}
__global__ void k_scan2() {   // parallel exclusive scan of 98 block sums
    __shared__ int s[128];
    int t = threadIdx.x;
    int v = (t < 98) ? g_bsum[t] : 0;
    s[t] = v;
    __syncthreads();
    #pragma unroll
    for (int d = 1; d < 128; d <<= 1) {
        int x = (t >= d) ? s[t - d] : 0;
        __syncthreads();
        s[t] += x;
        __syncthreads();
    }
    if (t < 98) g_bsum[t] = s[t] - v;
}
__global__ void k_scan3() {   // finalize offsets AND write cursors
    int t = threadIdx.x;
    int i = blockIdx.x * 1024 + t;
    if (i < NN) {
        int v = g_off[i + 1] + g_bsum[blockIdx.x];
        g_off[i + 1] = v;
        g_cur[i + 1] = v;
    }
    if (i == 0) { g_off[0] = 0; g_cur[0] = 0; }
}
__global__ void k_scatter(const int* __restrict__ src, const int* __restrict__ dst,
                          const int* __restrict__ ety) {
    int e = blockIdx.x * 256 + threadIdx.x;
    if (e < NE) {
        int d = __ldg(&dst[e]);
        int pos = atomicAdd(&g_cur[d], 1);
        g_csr[pos] = (unsigned)__ldg(&src[e]) | ((unsigned)__ldg(&ety[e]) << 20);
    }
}

// ---------------- weight transpose + tf32 rounding ----------------
__global__ void k_wt(const float* __restrict__ W, const float* __restrict__ Ws) {
    int idx = blockIdx.x * 256 + threadIdx.x;
    if (idx < LL * DD * KK) {
        int l = idx / (DD * KK);
        int rem = idx % (DD * KK);
        int j = rem / KK;
        int k = rem % KK;
        float v = (k < 384)
            ? W[(((size_t)l * 3 + (k >> 7)) * DD + (k & 127)) * DD + j]
            : Ws[((size_t)l * DD + (k - 384)) * DD + j];
        (&g_bt[0][0][0])[idx] = rna_tf32(v);
    }
}

// ---------------- rna copy of features (one-time, layer-0 input) ----------------
__global__ void k_frna(const float* __restrict__ feat) {
    size_t i = (size_t)blockIdx.x * 256 + threadIdx.x;
    if (i < (size_t)NN * DD) g_hf[i] = rna_tf32(feat[i]);
}

// ---------------- per-relation aggregation (one warp per node, no atomics) ------
__global__ void __launch_bounds__(256) k_agg(const float4* __restrict__ h4) {
    int gw = (blockIdx.x * blockDim.x + threadIdx.x) >> 5;
    int lane = threadIdx.x & 31;
    if (gw >= NN) return;
    int e0 = g_off[gw], e1 = g_off[gw + 1];
    float4 a0 = {0, 0, 0, 0}, a1 = {0, 0, 0, 0}, a2 = {0, 0, 0, 0};

    auto acc = [&](unsigned t, const float4& v) {
        if (t == 0)      { a0.x += v.x; a0.y += v.y; a0.z += v.z; a0.w += v.w; }
        else if (t == 1) { a1.x += v.x; a1.y += v.y; a1.z += v.z; a1.w += v.w; }
        else             { a2.x += v.x; a2.y += v.y; a2.z += v.z; a2.w += v.w; }
    };

    int e = e0;
    for (; e + 3 < e1; e += 4) {
        unsigned p0 = __ldcs(&g_csr[e]);
        unsigned p1 = __ldcs(&g_csr[e + 1]);
        unsigned p2 = __ldcs(&g_csr[e + 2]);
        unsigned p3 = __ldcs(&g_csr[e + 3]);
        float4 v0 = __ldg(&h4[(size_t)(p0 & 0xFFFFFu) * 32 + lane]);
        float4 v1 = __ldg(&h4[(size_t)(p1 & 0xFFFFFu) * 32 + lane]);
        float4 v2 = __ldg(&h4[(size_t)(p2 & 0xFFFFFu) * 32 + lane]);
        float4 v3 = __ldg(&h4[(size_t)(p3 & 0xFFFFFu) * 32 + lane]);
        acc(p0 >> 20, v0);
        acc(p1 >> 20, v1);
        acc(p2 >> 20, v2);
        acc(p3 >> 20, v3);
    }
    for (; e < e1; e++) {
        unsigned p0 = __ldcs(&g_csr[e]);
        float4 v0 = __ldg(&h4[(size_t)(p0 & 0xFFFFFu) * 32 + lane]);
        acc(p0 >> 20, v0);
    }

    auto rna4 = [](float4 v) {
        float4 r;
        r.x = rna_tf32(v.x); r.y = rna_tf32(v.y); r.z = rna_tf32(v.z); r.w = rna_tf32(v.w);
        return r;
    };
    float4* o = reinterpret_cast<float4*>(g_agg) + (size_t)gw * 96;   // 384 floats
    if (gw < CUT) {   // bulk: evict-first (protect h residency)
        __stcs(&o[lane],      rna4(a0));
        __stcs(&o[32 + lane], rna4(a1));
        __stcs(&o[64 + lane], rna4(a2));
    } else {          // tail: evict-normal (reverse-order gemm reads it from L2)
        o[lane]      = rna4(a0);
        o[32 + lane] = rna4(a1);
        o[64 + lane] = rna4(a2);
    }
}

// ---------------- mma.sync tf32 GEMM: [NNP x 512] @ Bt[l]^T -> [NNP x 128] ------
// A: kc 0..11 from g_agg (384-wide), kc 12..15 from hin (tf32-valued h, L2-hot).
// CTA tile 128x128, 8 warps (4m x 2n), 3-stage cp.async ring, 2 CTAs/SM.
// Tiles processed in REVERSE so the freshest agg tail is read while L2-resident.
static constexpr int GM_STAGES  = 3;
static constexpr int ROW_PAD    = 36;
static constexpr int TILE_FLTS  = 128 * ROW_PAD;
static constexpr int STAGE_FLTS = 2 * TILE_FLTS;
static constexpr int GEMM_SMEM  = GM_STAGES * STAGE_FLTS * 4;  // 110592 bytes

__device__ __forceinline__ void mma_tf32_16x8x8(float c[4],
                                                uint32_t a0, uint32_t a1, uint32_t a2, uint32_t a3,
                                                uint32_t b0, uint32_t b1) {
    asm volatile(
        "mma.sync.aligned.m16n8k8.row.col.f32.tf32.tf32.f32 "
        "{%0,%1,%2,%3}, {%4,%5,%6,%7}, {%8,%9}, {%0,%1,%2,%3};"
        : "+f"(c[0]), "+f"(c[1]), "+f"(c[2]), "+f"(c[3])
        : "r"(a0), "r"(a1), "r"(a2), "r"(a3), "r"(b0), "r"(b1));
}

__global__ void __launch_bounds__(256, 2)
k_gemm(int layer, const float* __restrict__ hin, const float* __restrict__ bias,
       float* __restrict__ hout, int do_rna) {
    extern __shared__ float sm[];
    uint32_t smaddr = smem_u32(sm);

    int tid = threadIdx.x, wid = tid >> 5, lane = tid & 31;
    int warp_m = wid >> 1, warp_n = wid & 1;
    int g = lane >> 2, q = lane & 3;

    int tile = NTILE - 1 - blockIdx.x;           // reverse order
    size_t row0 = (size_t)tile * 128;
    const float* B = &g_bt[layer][0][0];

    uint64_t pol;
    asm volatile("createpolicy.fractional.L2::evict_first.b64 %0;" : "=l"(pol));

    int r_ld[4], c_ld[4];
    #pragma unroll
    for (int i = 0; i < 4; i++) {
        int u = tid + i * 256;
        r_ld[i] = u >> 3;
        c_ld[i] = u & 7;
    }

    auto load_chunk = [&](int kc) {
        int st = kc % GM_STAGES;
        uint32_t sA = smaddr + (uint32_t)(st * STAGE_FLTS) * 4u;
        uint32_t sB = sA + (uint32_t)TILE_FLTS * 4u;
        #pragma unroll
        for (int i = 0; i < 4; i++) {
            const float* gsrc = (kc < 12)
                ? g_agg + (row0 + (size_t)r_ld[i]) * KA + kc * 32 + c_ld[i] * 4
                : hin   + (row0 + (size_t)r_ld[i]) * DD + (kc - 12) * 32 + c_ld[i] * 4;
            uint32_t d = sA + (uint32_t)(r_ld[i] * ROW_PAD + c_ld[i] * 4) * 4u;
            asm volatile("cp.async.cg.shared.global.L2::cache_hint [%0], [%1], 16, %2;"
                         :: "r"(d), "l"(gsrc), "l"(pol));
        }
        #pragma unroll
        for (int i = 0; i < 4; i++) {
            const float* gsrc = B + (size_t)r_ld[i] * KK + kc * 32 + c_ld[i] * 4;
            uint32_t d = sB + (uint32_t)(r_ld[i] * ROW_PAD + c_ld[i] * 4) * 4u;
            asm volatile("cp.async.cg.shared.global [%0], [%1], 16;" :: "r"(d), "l"(gsrc));
        }
        asm volatile("cp.async.commit_group;" ::: "memory");
    };

    float acc[2][8][4];
    #pragma unroll
    for (int mt = 0; mt < 2; mt++)
        #pragma unroll
        for (int nt = 0; nt < 8; nt++)
            #pragma unroll
            for (int v = 0; v < 4; v++) acc[mt][nt][v] = 0.0f;

    load_chunk(0);
    load_chunk(1);

    const uint32_t* smu = reinterpret_cast<const uint32_t*>(sm);

    #pragma unroll
    for (int kc = 0; kc < 16; kc++) {
        if (kc < 14) asm volatile("cp.async.wait_group 1;" ::: "memory");
        else         asm volatile("cp.async.wait_group 0;" ::: "memory");
        __syncthreads();

        if (kc + 2 < 16) load_chunk(kc + 2);

        int st = kc % GM_STAGES;
        const uint32_t* tA = smu + st * STAGE_FLTS;
        const uint32_t* tB = tA + TILE_FLTS;

        #pragma unroll
        for (int k8 = 0; k8 < 4; k8++) {
            int k0 = k8 * 8;
            uint32_t af[2][4];
            #pragma unroll
            for (int mt = 0; mt < 2; mt++) {
                int rb = warp_m * 32 + mt * 16;
                af[mt][0] = tA[(rb + g)     * ROW_PAD + k0 + q];
                af[mt][1] = tA[(rb + g + 8) * ROW_PAD + k0 + q];
                af[mt][2] = tA[(rb + g)     * ROW_PAD + k0 + q + 4];
                af[mt][3] = tA[(rb + g + 8) * ROW_PAD + k0 + q + 4];
            }
            #pragma unroll
            for (int nt = 0; nt < 8; nt++) {
                int nb = warp_n * 64 + nt * 8;
                uint32_t b0 = tB[(nb + g) * ROW_PAD + k0 + q];
                uint32_t b1 = tB[(nb + g) * ROW_PAD + k0 + q + 4];
                mma_tf32_16x8x8(acc[0][nt], af[0][0], af[0][1], af[0][2], af[0][3], b0, b1);
                mma_tf32_16x8x8(acc[1][nt], af[1][0], af[1][1], af[1][2], af[1][3], b0, b1);
            }
        }
        __syncthreads();
    }

    // epilogue: intermediate layers store rna(result) so h stays tf32-valued
    #pragma unroll
    for (int mt = 0; mt < 2; mt++) {
        size_t r0 = row0 + (size_t)(warp_m * 32 + mt * 16 + g);
        size_t r1 = r0 + 8;
        #pragma unroll
        for (int nt = 0; nt < 8; nt++) {
            int cb = warp_n * 64 + nt * 8 + q * 2;
            float bz0 = __ldg(&bias[cb]), bz1 = __ldg(&bias[cb + 1]);
            float v00 = acc[mt][nt][0] + bz0, v01 = acc[mt][nt][1] + bz1;
            float v10 = acc[mt][nt][2] + bz0, v11 = acc[mt][nt][3] + bz1;
            if (do_rna) {
                v00 = rna_tf32(v00); v01 = rna_tf32(v01);
                v10 = rna_tf32(v10); v11 = rna_tf32(v11);
            }
            if (r0 < NN) {
                hout[r0 * DD + cb]     = v00;
                hout[r0 * DD + cb + 1] = v01;
            }
            if (r1 < NN) {
                hout[r1 * DD + cb]     = v10;
                hout[r1 * DD + cb + 1] = v11;
            }
        }
    }
}

// ---------------- launch ----------------
extern "C" void kernel_launch(void* const* d_in, const int* in_sizes, int n_in,
                              void* d_out, int out_size) {
    const float* feat = (const float*)d_in[0];
    const float* W    = (const float*)d_in[1];
    const float* Ws   = (const float*)d_in[2];
    const float* bias = (const float*)d_in[3];
    const int*   src  = (const int*)d_in[4];
    const int*   dst  = (const int*)d_in[5];
    const int*   ety  = (const int*)d_in[6];
    float*       out  = (float*)d_out;

    static int smem_set = 0;
    if (!smem_set) {
        cudaFuncSetAttribute(k_gemm, cudaFuncAttributeMaxDynamicSharedMemorySize, GEMM_SMEM);
        smem_set = 1;
    }

    void* hsym = nullptr;
    cudaGetSymbolAddress(&hsym, g_h);
    float* h0 = (float*)hsym;
    float* h1 = h0 + (size_t)NNP * DD;
    void* hfsym = nullptr;
    cudaGetSymbolAddress(&hfsym, g_hf);
    float* hf = (float*)hfsym;

    // CSR by dst (graph fixed across layers -> build once per launch)
    k_zero_deg<<<(NN + 255) / 256, 256>>>();
    k_hist<<<(NE + 255) / 256, 256>>>(dst);
    k_scan1<<<98, 1024>>>();
    k_scan2<<<1, 128>>>();
    k_scan3<<<98, 1024>>>();
    k_scatter<<<(NE + 255) / 256, 256>>>(src, dst, ety);
    k_wt<<<(LL * DD * KK + 255) / 256, 256>>>(W, Ws);
    k_frna<<<(int)(((size_t)NN * DD + 255) / 256), 256>>>(feat);

    const float* hin = hf;
    for (int l = 0; l < LL; l++) {
        k_agg<<<(NN * 32 + 255) / 256, 256>>>((const float4*)hin);
        float* ho = (l == 2) ? out : (l == 0 ? h0 : h1);
        k_gemm<<<NTILE, 256, GEMM_SMEM>>>(l, hin, bias + l * DD, ho, (l < 2) ? 1 : 0);
        hin = ho;
    }
}